// round 16
// baseline (speedup 1.0000x reference)
#include <cuda_runtime.h>
#include <cuda_fp16.h>
#include <cstdint>

#define HH 128
#define WW 128
#define CHN 64
#define OCH 64
#define BATCH 4

#define Y2P 136          // y u32 pitch; 136 % 32 == 8 -> conflict-free a-LDS
#define YOFF 4           // left pad: px p at row offset 4+p (16B-aligned stores)

#define Y_U32   (128 * Y2P)                 // 17408 u32 (4 ir x 32 cpair rows)
#define W_U2    2304                        // uint2 per 16-ch chunk (9 taps x 256)
#define OFF_Y   0                           // bytes
#define OFF_W   (Y_U32 * 4)                 // 69632 (16B aligned)
#define OFF_FA  (OFF_W + 2 * W_U2 * 8)      // 106496
#define OFF_BI  (OFF_FA + 4 * Y2P * 4)      // 108672
#define SMEM_BYTES (OFF_BI + 256)           // 108928 -> 2 CTAs/SM (217856 <= 228KB)

__device__ __forceinline__ uint32_t pack_h2(float lo, float hi) {
    __half2 h = __floats2half2_rn(lo, hi);
    return *reinterpret_cast<uint32_t*>(&h);
}

__device__ __forceinline__ void mma_fp16(float* d, uint32_t a0, uint32_t a1,
                                         uint32_t a2, uint32_t a3,
                                         uint32_t b0, uint32_t b1) {
    asm volatile(
        "mma.sync.aligned.m16n8k16.row.col.f32.f16.f16.f32 "
        "{%0,%1,%2,%3}, {%4,%5,%6,%7}, {%8,%9}, {%0,%1,%2,%3};\n"
        : "+f"(d[0]), "+f"(d[1]), "+f"(d[2]), "+f"(d[3])
        : "r"(a0), "r"(a1), "r"(a2), "r"(a3), "r"(b0), "r"(b1));
}

__device__ __forceinline__ void cp_async16(uint32_t s_addr, const void* g) {
    asm volatile("cp.async.cg.shared.global [%0], [%1], 16;" :: "r"(s_addr), "l"(g));
}

// ---- prepacked fp16 k-paired weights, per 16-channel chunk (verified R12):
// g_w6[ch][t][j*32 + lane] (lane = 4*qid+tq, n = j*8+qid) = uint2
//   .x = h2( W[n][ch*16+2tq][t],   W[n][ch*16+2tq+1][t] )   -> b0 (k, k+1)
//   .y = h2( W[n][ch*16+2tq+8][t], W[n][ch*16+2tq+9][t] )   -> b1 (k+8, k+9)
__device__ __align__(16) uint2 g_w6[4 * W_U2];

__global__ void wt_prepack(const float* __restrict__ w) {
    int i = blockIdx.x * 256 + threadIdx.x;
    if (i >= 4 * W_U2) return;
    int tq  = i & 3;
    int qid = (i >> 2) & 7;
    int j   = (i >> 5) & 7;
    int t   = (i >> 8) % 9;
    int ch  = (i >> 8) / 9;
    int n   = j * 8 + qid;
    int c0  = ch * 16 + 2 * tq;
    uint2 v;
    v.x = pack_h2(w[(n * CHN + c0) * 9 + t],     w[(n * CHN + c0 + 1) * 9 + t]);
    v.y = pack_h2(w[(n * CHN + c0 + 8) * 9 + t], w[(n * CHN + c0 + 9) * 9 + t]);
    g_w6[i] = v;
}

// ============================ main kernel ============================
// CTA = (batch, row-pair). M = 256 px, N = 64, K = 576.
// ALL 64 channels of y resident in smem (written once) -> per-chunk y fills
// and their barriers are gone: 5 __syncthreads total. Weights double-buffered
// via cp.async with 1-chunk-ahead prefetch. Hot tap loop identical to the
// verified fp16 kernel.

__global__ __launch_bounds__(256, 2)
void conv_mma(const float* __restrict__ x,
              const float* __restrict__ alpha,
              const float* __restrict__ bias,
              const float* __restrict__ pa,
              const float* __restrict__ pb,
              const float* __restrict__ pc,
              float* __restrict__ out)
{
    extern __shared__ char smem[];
    uint32_t* y2_s = (uint32_t*)(smem + OFF_Y);   // [4 ir][32 cpair][Y2P] f16x2
    uint2*    w2_s = (uint2*)   (smem + OFF_W);   // [2 buf][9 t][256]
    float*    fa_s = (float*)   (smem + OFF_FA);  // [4 ir][Y2P]
    float*    bi_s = (float*)   (smem + OFF_BI);

    const int tid  = threadIdx.x;
    const int warp = tid >> 5;
    const int lane = tid & 31;
    const int qid  = lane >> 2;
    const int tq   = lane & 3;

    const int rp = blockIdx.x;
    const int b  = blockIdx.y;
    const int r0 = 2 * rp;

    const int lr  = warp >> 2;          // output row within pair
    const int px0 = (warp & 3) * 32;    // pixel block

    const uint32_t w_s_addr = (uint32_t)__cvta_generic_to_shared(w2_s);

    // ---- prologue: chunk 0 weights via cp.async (overlaps fa + y fill)
    {
        const char* src = (const char*)g_w6;
        #pragma unroll
        for (int i = 0; i < 5; i++) {
            int seg = tid + i * 256;
            if (seg < 1152) cp_async16(w_s_addr + seg * 16, src + seg * 16);
        }
        asm volatile("cp.async.commit_group;" ::: "memory");
    }

    // ---- f(alpha), bias, y pad-zeros
    {
        const float A = __ldg(pa), Bq = __ldg(pb), Cq = __ldg(pc);
        const float* ap = alpha + b * HH * WW;
        for (int i = tid; i < 4 * 128; i += 256) {
            int ir = i >> 7, px = i & 127;
            int gy = r0 - 1 + ir;
            float v = 0.0f;
            if ((unsigned)gy < HH) {
                float t = __ldg(ap + gy * WW + px);
                v = (A * t + Bq) * t + Cq;
            }
            fa_s[ir * Y2P + YOFF + px] = v;
        }
        #pragma unroll
        for (int q = 0; q < 4; q++) {   // zero u32 pads of all 128 rows
            int i = tid + q * 256;
            int r = i >> 3, o = i & 7;
            y2_s[r * Y2P + (o < 4 ? o : 128 + o)] = 0u;
        }
        if (tid < 64) bi_s[tid] = __ldg(bias + tid);
    }
    __syncthreads();   // fa/pads visible to the fill below

    // ---- ONE y fill: all 64 channels, premultiplied f16x2 pairs.
    // 4096 uint4 stores; idx -> row (ir*32 + cpair), px4.
    #pragma unroll 2
    for (int q = 0; q < 16; q++) {
        int idx = tid + q * 256;
        int row = idx >> 5;              // 0..127
        int ir  = row >> 5;              // 0..3
        int cp  = row & 31;              // 0..31 (channels 2cp, 2cp+1)
        int px4 = (idx & 31) * 4;
        int gy  = r0 - 1 + ir;
        float4 v0 = make_float4(0.f, 0.f, 0.f, 0.f);
        float4 v1 = v0;
        if ((unsigned)gy < HH) {
            const float* xp = x + (((b * CHN + 2 * cp) * HH) + gy) * WW + px4;
            v0 = *(const float4*)xp;
            v1 = *(const float4*)(xp + HH * WW);
        }
        float4 f = *(const float4*)(fa_s + ir * Y2P + YOFF + px4);
        uint4 s;
        s.x = pack_h2(v0.x * f.x, v1.x * f.x);
        s.y = pack_h2(v0.y * f.y, v1.y * f.y);
        s.z = pack_h2(v0.z * f.z, v1.z * f.z);
        s.w = pack_h2(v0.w * f.w, v1.w * f.w);
        *(uint4*)(y2_s + row * Y2P + YOFF + px4) = s;
    }

    float d[2][8][4];
    #pragma unroll
    for (int mi = 0; mi < 2; mi++)
        #pragma unroll
        for (int j = 0; j < 8; j++)
            #pragma unroll
            for (int r = 0; r < 4; r++) d[mi][j][r] = 0.0f;

    #pragma unroll 1
    for (int ch = 0; ch < 4; ch++) {
        asm volatile("cp.async.wait_group 0;" ::: "memory");  // this chunk's w landed
        __syncthreads();   // w visible CTA-wide; y fill visible (ch=0);
                           // prev chunk's reads of the other w buffer done

        // prefetch next chunk's weights into the other buffer (hidden under taps)
        if (ch < 3) {
            const char* src = (const char*)(g_w6 + (ch + 1) * W_U2);
            uint32_t dst = w_s_addr + ((ch + 1) & 1) * (W_U2 * 8);
            #pragma unroll
            for (int i = 0; i < 5; i++) {
                int seg = tid + i * 256;
                if (seg < 1152) cp_async16(dst + seg * 16, src + seg * 16);
            }
            asm volatile("cp.async.commit_group;" ::: "memory");
        }

        // ---- 9 taps, barrier-free (hot loop identical to verified R12)
        const uint2* wb = w2_s + (ch & 1) * W_U2 + lane;
        #pragma unroll 1
        for (int t = 0; t < 9; t++) {
            const int kt = t / 3, lt = t - 3 * kt;
            const uint32_t* ar0 = y2_s + ((lr + kt) * 32 + ch * 8 + tq) * Y2P
                                  + YOFF + px0 + lt - 1 + qid;
            const uint32_t* ar1 = ar0 + 4 * Y2P;          // cpair tq+4 (k+8)
            const uint2* wq = wb + t * 256;

            uint2 bv[8];
            #pragma unroll
            for (int j = 0; j < 8; j++) bv[j] = wq[j * 32];   // LDS.64, conflict-free

            #pragma unroll
            for (int mi = 0; mi < 2; mi++) {
                uint32_t a0 = ar0[mi * 16];          // (m,    k0..1)
                uint32_t a1 = ar0[mi * 16 + 8];      // (m+8,  k0..1)
                uint32_t a2 = ar1[mi * 16];          // (m,    k8..9)
                uint32_t a3 = ar1[mi * 16 + 8];      // (m+8,  k8..9)
                #pragma unroll
                for (int j = 0; j < 8; j++)
                    mma_fp16(d[mi][j], a0, a1, a2, a3, bv[j].x, bv[j].y);
            }
        }
    }

    // ---- epilogue (verified fragment map)
    const int imgrow = r0 + lr;
    #pragma unroll
    for (int j = 0; j < 8; j++) {
        const int o0 = j * 8 + 2 * tq;
        const float b0v = bi_s[o0], b1v = bi_s[o0 + 1];
        float* p0 = out + (((b * OCH + o0) * HH) + imgrow) * WW;
        #pragma unroll
        for (int mi = 0; mi < 2; mi++) {
            const int px = px0 + mi * 16 + qid;
            p0[px]               = d[mi][j][0] + b0v;
            p0[HH * WW + px]     = d[mi][j][1] + b1v;
            p0[px + 8]           = d[mi][j][2] + b0v;
            p0[HH * WW + px + 8] = d[mi][j][3] + b1v;
        }
    }
}

// ============================ launch ============================
extern "C" void kernel_launch(void* const* d_in, const int* in_sizes, int n_in,
                              void* d_out, int out_size)
{
    const float* x     = (const float*)d_in[0];
    const float* alpha = (const float*)d_in[1];
    const float* wgt   = (const float*)d_in[2];
    const float* bias  = (const float*)d_in[3];
    const float* pa    = (const float*)d_in[4];
    const float* pb    = (const float*)d_in[5];
    const float* pc    = (const float*)d_in[6];
    float* out = (float*)d_out;

    wt_prepack<<<(4 * W_U2 + 255) / 256, 256>>>(wgt);

    cudaFuncSetAttribute(conv_mma,
                         cudaFuncAttributeMaxDynamicSharedMemorySize, SMEM_BYTES);
    dim3 grid(HH / 2, BATCH);   // 64 x 4 = 256 CTAs, single wave at 2 CTA/SM
    conv_mma<<<grid, 256, SMEM_BYTES>>>(x, alpha, bias, pa, pb, pc, out);
}